// round 1
// baseline (speedup 1.0000x reference)
#include <cuda_runtime.h>
#include <math.h>
#include <float.h>

#define B_   2
#define S_   2048
#define H_   2048
#define NH_  16
#define HD_  128
#define W_   512
#define LN_EPS 1e-6f

#define ROWS_ (B_ * S_)          // 4096
#define QK_SCALE 0.08838834764831845f   // 1/sqrt(128)

// ---------------- scratch (device globals; no allocations allowed) ----------
__device__ float g_y  [(size_t)B_ * S_ * H_];            // LN output
__device__ float g_q  [(size_t)B_ * S_ * NH_ * HD_];
__device__ float g_k  [(size_t)B_ * S_ * NH_ * HD_];
__device__ float g_v  [(size_t)B_ * S_ * NH_ * HD_];
__device__ float g_s  [(size_t)B_ * NH_ * S_ * S_];      // scores / attn (536 MB)
__device__ float g_ctx[(size_t)B_ * S_ * NH_ * HD_];     // attn @ V

// ---------------- LayerNorm: one block per row ------------------------------
__global__ __launch_bounds__(256) void ln_kernel(const float* __restrict__ x,
                                                 const float* __restrict__ sc,
                                                 const float* __restrict__ bi) {
    __shared__ float red[256];
    int row = blockIdx.x;
    int t = threadIdx.x;
    const float* xr = x + (size_t)row * H_;
    float* yr = g_y + (size_t)row * H_;

    float v[8];
    float s = 0.f;
#pragma unroll
    for (int i = 0; i < 8; i++) { v[i] = xr[t + i * 256]; s += v[i]; }

    red[t] = s; __syncthreads();
#pragma unroll
    for (int o = 128; o > 0; o >>= 1) { if (t < o) red[t] += red[t + o]; __syncthreads(); }
    float mu = red[0] * (1.0f / H_);
    __syncthreads();

    float s2 = 0.f;
#pragma unroll
    for (int i = 0; i < 8; i++) { float d = v[i] - mu; s2 += d * d; }
    red[t] = s2; __syncthreads();
#pragma unroll
    for (int o = 128; o > 0; o >>= 1) { if (t < o) red[t] += red[t + o]; __syncthreads(); }
    float w = rsqrtf(red[0] * (1.0f / H_) + LN_EPS);

#pragma unroll
    for (int i = 0; i < 8; i++) {
        int c = t + i * 256;
        yr[c] = (v[i] - mu) * w * sc[c] + bi[c];
    }
}

// ---------------- generic batched NN SGEMM, 128x128x8, 8x8/thread -----------
// batch index z decomposed as zb = z/NH, zn = z%NH so (b,n)-strided tensors work.
__global__ __launch_bounds__(256) void sgemm_nn(
    const float* __restrict__ A, const float* __restrict__ Bm,
    const float* __restrict__ bias, float* __restrict__ C,
    int K, int lda, int ldb, int ldc,
    long sAb, long sAn, long sBb, long sBn, long sCb, long sCn,
    float alpha)
{
    __shared__ float As[8][128];
    __shared__ float Bs[8][128];

    int z = blockIdx.z;
    int zb = z / NH_, zn = z % NH_;
    A  += (size_t)zb * sAb + (size_t)zn * sAn;
    Bm += (size_t)zb * sBb + (size_t)zn * sBn;
    C  += (size_t)zb * sCb + (size_t)zn * sCn;

    int tid  = threadIdx.x;
    int brow = blockIdx.y * 128;
    int bcol = blockIdx.x * 128;
    int tr = (tid >> 4) << 3;
    int tc = (tid & 15) << 3;
    int ar = tid >> 1, ac = (tid & 1) << 2;    // A tile: 128 rows x 8 k
    int br = tid >> 5, bc = (tid & 31) << 2;   // B tile: 8 k x 128 cols

    float acc[8][8];
#pragma unroll
    for (int i = 0; i < 8; i++)
#pragma unroll
        for (int j = 0; j < 8; j++) acc[i][j] = 0.f;

    for (int k0 = 0; k0 < K; k0 += 8) {
        float4 a4 = *(const float4*)(A + (size_t)(brow + ar) * lda + (k0 + ac));
        As[ac + 0][ar] = a4.x; As[ac + 1][ar] = a4.y;
        As[ac + 2][ar] = a4.z; As[ac + 3][ar] = a4.w;
        float4 b4 = *(const float4*)(Bm + (size_t)(k0 + br) * ldb + (bcol + bc));
        *(float4*)(&Bs[br][bc]) = b4;
        __syncthreads();

#pragma unroll
        for (int kk = 0; kk < 8; kk++) {
            float af[8], bf[8];
            *(float4*)(af)     = *(const float4*)(&As[kk][tr]);
            *(float4*)(af + 4) = *(const float4*)(&As[kk][tr + 4]);
            *(float4*)(bf)     = *(const float4*)(&Bs[kk][tc]);
            *(float4*)(bf + 4) = *(const float4*)(&Bs[kk][tc + 4]);
#pragma unroll
            for (int i = 0; i < 8; i++)
#pragma unroll
                for (int j = 0; j < 8; j++)
                    acc[i][j] = fmaf(af[i], bf[j], acc[i][j]);
        }
        __syncthreads();
    }

#pragma unroll
    for (int i = 0; i < 8; i++)
#pragma unroll
        for (int j = 0; j < 8; j++) {
            float v = acc[i][j];
            if (bias) v += bias[bcol + tc + j];
            v *= alpha;
            C[(size_t)(brow + tr + i) * ldc + (bcol + tc + j)] = v;
        }
}

// ---------------- scores = Q K^T with inverted-window mask fused -------------
// batch z = b*NH + n; A rows = queries, B rows = keys, both d-contiguous.
__global__ __launch_bounds__(256) void scores_kernel(const float* __restrict__ q,
                                                     const float* __restrict__ kmat) {
    __shared__ float As[32][132];   // [d][i]
    __shared__ float Bs[32][132];   // [d][j]

    int z = blockIdx.z;
    int b = z >> 4, n = z & 15;
    const float* A  = q    + (size_t)b * S_ * (NH_ * HD_) + (size_t)n * HD_;
    const float* Bp = kmat + (size_t)b * S_ * (NH_ * HD_) + (size_t)n * HD_;

    int tid  = threadIdx.x;
    int brow = blockIdx.y * 128;   // query tile
    int bcol = blockIdx.x * 128;   // key tile
    int tr = (tid >> 4) << 3;
    int tc = (tid & 15) << 3;

    float acc[8][8];
#pragma unroll
    for (int i = 0; i < 8; i++)
#pragma unroll
        for (int j = 0; j < 8; j++) acc[i][j] = 0.f;

    for (int k0 = 0; k0 < HD_; k0 += 32) {
#pragma unroll
        for (int l = 0; l < 4; l++) {
            int idx = tid + l * 256;
            int row = idx >> 3;            // 0..127
            int c4  = (idx & 7) << 2;      // 0..28
            float4 a4 = *(const float4*)(A  + (size_t)(brow + row) * 2048 + k0 + c4);
            As[c4 + 0][row] = a4.x; As[c4 + 1][row] = a4.y;
            As[c4 + 2][row] = a4.z; As[c4 + 3][row] = a4.w;
            float4 b4 = *(const float4*)(Bp + (size_t)(bcol + row) * 2048 + k0 + c4);
            Bs[c4 + 0][row] = b4.x; Bs[c4 + 1][row] = b4.y;
            Bs[c4 + 2][row] = b4.z; Bs[c4 + 3][row] = b4.w;
        }
        __syncthreads();

#pragma unroll
        for (int kx = 0; kx < 32; kx++) {
            float af[8], bf[8];
            *(float4*)(af)     = *(const float4*)(&As[kx][tr]);
            *(float4*)(af + 4) = *(const float4*)(&As[kx][tr + 4]);
            *(float4*)(bf)     = *(const float4*)(&Bs[kx][tc]);
            *(float4*)(bf + 4) = *(const float4*)(&Bs[kx][tc + 4]);
#pragma unroll
            for (int i = 0; i < 8; i++)
#pragma unroll
                for (int j = 0; j < 8; j++)
                    acc[i][j] = fmaf(af[i], bf[j], acc[i][j]);
        }
        __syncthreads();
    }

    float* out = g_s + (size_t)z * S_ * S_;
#pragma unroll
    for (int i = 0; i < 8; i++) {
        int gi = brow + tr + i;
#pragma unroll
        for (int j = 0; j < 8; j++) {
            int gj = bcol + tc + j;
            // Reference keeps OUT-of-window scores; in-window entries get big_neg.
            bool in_win = (gi >= gj) && (gi - gj < W_);
            out[(size_t)gi * S_ + gj] = in_win ? -FLT_MAX : acc[i][j];
        }
    }
}

// ---------------- softmax over last dim of g_s (rows of 2048) ----------------
__global__ __launch_bounds__(256) void softmax_kernel() {
    __shared__ float red[256];
    size_t base = (size_t)blockIdx.x * S_;
    int t = threadIdx.x;

    float v[8];
    float m = -FLT_MAX;
#pragma unroll
    for (int i = 0; i < 8; i++) { v[i] = g_s[base + t + i * 256]; m = fmaxf(m, v[i]); }

    red[t] = m; __syncthreads();
#pragma unroll
    for (int o = 128; o > 0; o >>= 1) { if (t < o) red[t] = fmaxf(red[t], red[t + o]); __syncthreads(); }
    m = red[0]; __syncthreads();

    float s = 0.f;
#pragma unroll
    for (int i = 0; i < 8; i++) { v[i] = __expf(v[i] - m); s += v[i]; }
    red[t] = s; __syncthreads();
#pragma unroll
    for (int o = 128; o > 0; o >>= 1) { if (t < o) red[t] += red[t + o]; __syncthreads(); }
    float inv = 1.0f / red[0];

#pragma unroll
    for (int i = 0; i < 8; i++) g_s[base + t + i * 256] = v[i] * inv;
}

// ---------------- launch ------------------------------------------------------
extern "C" void kernel_launch(void* const* d_in, const int* in_sizes, int n_in,
                              void* d_out, int out_size) {
    const float* x        = (const float*)d_in[0];
    const float* ln_scale = (const float*)d_in[1];
    const float* ln_bias  = (const float*)d_in[2];
    const float* wq       = (const float*)d_in[3];
    const float* bq       = (const float*)d_in[4];
    const float* wk       = (const float*)d_in[5];
    const float* bk       = (const float*)d_in[6];
    const float* wv       = (const float*)d_in[7];
    const float* bv       = (const float*)d_in[8];
    const float* wo       = (const float*)d_in[9];
    const float* bo       = (const float*)d_in[10];
    float* out = (float*)d_out;

    float *yv, *qv, *kv, *vv, *sv, *cv;
    cudaGetSymbolAddress((void**)&yv, g_y);
    cudaGetSymbolAddress((void**)&qv, g_q);
    cudaGetSymbolAddress((void**)&kv, g_k);
    cudaGetSymbolAddress((void**)&vv, g_v);
    cudaGetSymbolAddress((void**)&sv, g_s);
    cudaGetSymbolAddress((void**)&cv, g_ctx);

    // 1) LayerNorm
    ln_kernel<<<ROWS_, 256>>>(x, ln_scale, ln_bias);

    // 2) Q/K/V projections: [4096,2048] x [2048,2048]
    dim3 gProj(H_ / 128, ROWS_ / 128, 1);
    sgemm_nn<<<gProj, 256>>>(yv, wq, bq, qv, H_, H_, H_, H_,
                             0, 0, 0, 0, 0, 0, QK_SCALE);
    sgemm_nn<<<gProj, 256>>>(yv, wk, bk, kv, H_, H_, H_, H_,
                             0, 0, 0, 0, 0, 0, 1.0f);
    sgemm_nn<<<gProj, 256>>>(yv, wv, bv, vv, H_, H_, H_, H_,
                             0, 0, 0, 0, 0, 0, 1.0f);

    // 3) scores = Q K^T (+ inverted-window mask), batch = B*NH = 32
    dim3 gScores(S_ / 128, S_ / 128, B_ * NH_);
    scores_kernel<<<gScores, 256>>>(qv, kv);

    // 4) softmax over keys
    softmax_kernel<<<B_ * NH_ * S_, 256>>>();

    // 5) ctx = attn @ V : per (b,n) [2048,2048] x [2048,128]
    dim3 gPV(HD_ / 128, S_ / 128, B_ * NH_);
    sgemm_nn<<<gPV, 256>>>(sv, vv, (const float*)nullptr, cv,
                           S_, S_, NH_ * HD_, NH_ * HD_,
                           (long)NH_ * S_ * S_, (long)S_ * S_,   // A strides (b, n)
                           (long)S_ * NH_ * HD_, (long)HD_,      // B strides
                           (long)S_ * NH_ * HD_, (long)HD_,      // C strides
                           1.0f);

    // 6) out = ctx @ Wo + bo : [4096,2048] x [2048,2048]
    sgemm_nn<<<gProj, 256>>>(cv, wo, bo, out, H_, H_, H_, H_,
                             0, 0, 0, 0, 0, 0, 1.0f);
}

// round 8
// speedup vs baseline: 2.2290x; 2.2290x over previous
#include <cuda_runtime.h>
#include <cuda_bf16.h>
#include <math.h>
#include <float.h>
#include <stdint.h>

#define B_   2
#define S_   2048
#define H_   2048
#define NH_  16
#define HD_  128
#define W_   512
#define LN_EPS 1e-6f
#define ROWS_ 4096
#define K3H  (3*H_)       // 6144
#define K3D  (3*HD_)      // 384
#define QK_SCALE 0.08838834764831845f

// ----------------------------- scratch --------------------------------------
__device__ __nv_bfloat16 g_yp  [(size_t)ROWS_ * K3H];           // LN out, aug A (hi,hi,lo)
__device__ __nv_bfloat16 g_wqp [(size_t)K3H * H_];              // weights, aug B (hi,lo,hi)
__device__ __nv_bfloat16 g_wkp [(size_t)K3H * H_];
__device__ __nv_bfloat16 g_wvp [(size_t)K3H * H_];
__device__ __nv_bfloat16 g_wop [(size_t)K3H * H_];
__device__ float         g_q   [(size_t)ROWS_ * H_];
__device__ float         g_k   [(size_t)ROWS_ * H_];
__device__ float         g_v   [(size_t)ROWS_ * H_];
__device__ __nv_bfloat16 g_qp  [(size_t)B_*NH_*S_ * K3D];       // [b][n][s][384] aug A
__device__ __nv_bfloat16 g_kp  [(size_t)B_*NH_*S_ * K3D];       // [b][n][s][384] aug B
__device__ __nv_bfloat16 g_vp  [(size_t)B_ * K3H * H_];         // [b][3S][NH*HD] aug B
__device__ float         g_s   [(size_t)B_*NH_*S_*S_];          // scores fp32
__device__ __nv_bfloat16 g_attnp[(size_t)B_*NH_*S_ * K3H];      // [z][s][6144] aug A
__device__ float         g_ctx [(size_t)ROWS_ * H_];
__device__ __nv_bfloat16 g_ctxp[(size_t)ROWS_ * K3H];           // aug A

// ----------------------------- helpers --------------------------------------
__device__ __forceinline__ void split2(float x, __nv_bfloat16& h, __nv_bfloat16& l) {
    h = __float2bfloat16(x);
    l = __float2bfloat16(x - __bfloat162float(h));
}
__device__ __forceinline__ uint32_t sptr(const void* p) {
    return (uint32_t)__cvta_generic_to_shared(p);
}
#define CPA(dst, src)  asm volatile("cp.async.cg.shared.global [%0], [%1], 16;\n" :: "r"(dst), "l"(src))
#define CPCOMMIT()     asm volatile("cp.async.commit_group;\n")
#define CPWAIT1()      asm volatile("cp.async.wait_group 1;\n")
#define CPWAIT0()      asm volatile("cp.async.wait_group 0;\n")

// ---------------- LayerNorm fused with split-aug write -----------------------
__global__ __launch_bounds__(256) void ln_aug_kernel(const float* __restrict__ x,
                                                     const float* __restrict__ sc,
                                                     const float* __restrict__ bi) {
    __shared__ float red[256];
    int row = blockIdx.x;
    int t = threadIdx.x;
    const float* xr = x + (size_t)row * H_;
    __nv_bfloat16* yr = g_yp + (size_t)row * K3H;

    float v[8];
    float s = 0.f;
#pragma unroll
    for (int i = 0; i < 8; i++) { v[i] = xr[t + i * 256]; s += v[i]; }
    red[t] = s; __syncthreads();
#pragma unroll
    for (int o = 128; o > 0; o >>= 1) { if (t < o) red[t] += red[t + o]; __syncthreads(); }
    float mu = red[0] * (1.0f / H_);
    __syncthreads();
    float s2 = 0.f;
#pragma unroll
    for (int i = 0; i < 8; i++) { float d = v[i] - mu; s2 += d * d; }
    red[t] = s2; __syncthreads();
#pragma unroll
    for (int o = 128; o > 0; o >>= 1) { if (t < o) red[t] += red[t + o]; __syncthreads(); }
    float w = rsqrtf(red[0] * (1.0f / H_) + LN_EPS);

#pragma unroll
    for (int i = 0; i < 8; i++) {
        int c = t + i * 256;
        float y = (v[i] - mu) * w * sc[c] + bi[c];
        __nv_bfloat16 h, l; split2(y, h, l);
        yr[c] = h; yr[c + H_] = h; yr[c + 2 * H_] = l;      // (hi, hi, lo)
    }
}

// ---------------- weight augmentation: [2048x2048] -> [6144x2048] (hi,lo,hi) --
__global__ __launch_bounds__(256) void w_aug_kernel(const float* __restrict__ w,
                                                    __nv_bfloat16* __restrict__ d) {
    size_t idx = (size_t)blockIdx.x * 256 + threadIdx.x;   // over 2048*2048
    float x = w[idx];
    __nv_bfloat16 h, l; split2(x, h, l);
    const size_t blk = (size_t)H_ * H_;
    d[idx] = h; d[idx + blk] = l; d[idx + 2 * blk] = h;
}

// ---------------- q/k aug: [b][s][n][d] fp32 -> [b][n][s][384] ----------------
// patA=true => (hi,hi,lo); patA=false => (hi,lo,hi)
__global__ __launch_bounds__(256) void qk_aug_kernel(const float* __restrict__ src,
                                                     __nv_bfloat16* __restrict__ dst,
                                                     int patA) {
    size_t idx = (size_t)blockIdx.x * 256 + threadIdx.x;   // over 2*2048*16*128
    float x = src[idx];
    int d = idx & 127;
    int n = (idx >> 7) & 15;
    int s = (idx >> 11) & 2047;
    int b = (int)(idx >> 22);
    __nv_bfloat16 h, l; split2(x, h, l);
    size_t base = (((size_t)(b * NH_ + n) * S_) + s) * K3D + d;
    dst[base] = h;
    dst[base + HD_]     = patA ? h : l;
    dst[base + 2 * HD_] = patA ? l : h;
}

// ---------------- v aug: [b][s][n][d] fp32 -> [b][3S][2048] (hi,lo,hi rows) ---
__global__ __launch_bounds__(256) void v_aug_kernel(const float* __restrict__ src,
                                                    __nv_bfloat16* __restrict__ dst) {
    size_t idx = (size_t)blockIdx.x * 256 + threadIdx.x;
    float x = src[idx];
    int c = (int)(idx & 2047);           // n*128+d
    int s = (idx >> 11) & 2047;
    int b = (int)(idx >> 22);
    __nv_bfloat16 h, l; split2(x, h, l);
    size_t base = (size_t)b * K3H * H_ + (size_t)s * H_ + c;
    const size_t blk = (size_t)S_ * H_;
    dst[base] = h; dst[base + blk] = l; dst[base + 2 * blk] = h;
}

// ---------------- ctx aug: [4096][2048] -> [4096][6144] (hi,hi,lo) ------------
__global__ __launch_bounds__(256) void ctx_aug_kernel(const float* __restrict__ src,
                                                      __nv_bfloat16* __restrict__ dst) {
    size_t idx = (size_t)blockIdx.x * 256 + threadIdx.x;
    float x = src[idx];
    int r = (int)(idx >> 11);
    int c = (int)(idx & 2047);
    __nv_bfloat16 h, l; split2(x, h, l);
    size_t base = (size_t)r * K3H + c;
    dst[base] = h; dst[base + H_] = h; dst[base + 2 * H_] = l;
}

// ---------------- softmax fused with split-aug write --------------------------
__global__ __launch_bounds__(256) void softmax_aug_kernel() {
    __shared__ float red[256];
    size_t rowid = blockIdx.x;                  // 32*2048 rows
    const float* src = g_s + rowid * S_;
    __nv_bfloat16* dst = g_attnp + rowid * (size_t)K3H;
    int t = threadIdx.x;

    float v[8];
    float m = -FLT_MAX;
#pragma unroll
    for (int i = 0; i < 8; i++) { v[i] = src[t + i * 256]; m = fmaxf(m, v[i]); }
    red[t] = m; __syncthreads();
#pragma unroll
    for (int o = 128; o > 0; o >>= 1) { if (t < o) red[t] = fmaxf(red[t], red[t + o]); __syncthreads(); }
    m = red[0]; __syncthreads();
    float s = 0.f;
#pragma unroll
    for (int i = 0; i < 8; i++) { v[i] = __expf(v[i] - m); s += v[i]; }
    red[t] = s; __syncthreads();
#pragma unroll
    for (int o = 128; o > 0; o >>= 1) { if (t < o) red[t] += red[t + o]; __syncthreads(); }
    float inv = 1.0f / red[0];

#pragma unroll
    for (int i = 0; i < 8; i++) {
        int c = t + i * 256;
        float e = v[i] * inv;
        __nv_bfloat16 h, l; split2(e, h, l);
        dst[c] = h; dst[c + S_] = h; dst[c + 2 * S_] = l;   // (hi,hi,lo)
    }
}

// ---------------- bf16 MMA GEMM: 128x128x32 tiles, 8 warps --------------------
// BT=true : B is [N x K] row-major (NT GEMM, e.g. Q*K^T)
// BT=false: B is [K x N] row-major (NN GEMM)
template<bool BT, bool MASK>
__global__ __launch_bounds__(256) void mma_gemm(
    const __nv_bfloat16* __restrict__ A, const __nv_bfloat16* __restrict__ Bm,
    const float* __restrict__ bias, float* __restrict__ C,
    int K, int lda, int ldb, int ldc,
    long sAb, long sAn, long sBb, long sBn, long sCb, long sCn,
    float alpha)
{
    __shared__ __nv_bfloat16 As[2][128 * 40];
    __shared__ __nv_bfloat16 Bs[2][128 * 40];   // NN mode uses only 32*136

    int z = blockIdx.z, zb = z / NH_, zn = z % NH_;
    A  += (size_t)zb * sAb + (size_t)zn * sAn;
    Bm += (size_t)zb * sBb + (size_t)zn * sBn;
    C  += (size_t)zb * sCb + (size_t)zn * sCn;

    int tid = threadIdx.x;
    int warp = tid >> 5, lane = tid & 31;
    int brow = blockIdx.y * 128, bcol = blockIdx.x * 128;
    int wm = (warp & 1) * 64, wn = (warp >> 1) * 32;

    float acc[4][4][4];
#pragma unroll
    for (int i = 0; i < 4; i++)
#pragma unroll
        for (int j = 0; j < 4; j++)
#pragma unroll
            for (int r = 0; r < 4; r++) acc[i][j][r] = 0.f;

    int KT = K >> 5;

    auto load_stage = [&](int buf, int kt) {
#pragma unroll
        for (int i = 0; i < 2; i++) {
            int idx = tid + 256 * i;
            int r = idx >> 2, c = (idx & 3) << 3;
            CPA(sptr(&As[buf][r * 40 + c]),
                A + (size_t)(brow + r) * lda + (kt << 5) + c);
        }
        if (BT) {
#pragma unroll
            for (int i = 0; i < 2; i++) {
                int idx = tid + 256 * i;
                int r = idx >> 2, c = (idx & 3) << 3;
                CPA(sptr(&Bs[buf][r * 40 + c]),
                    Bm + (size_t)(bcol + r) * ldb + (kt << 5) + c);
            }
        } else {
#pragma unroll
            for (int i = 0; i < 2; i++) {
                int idx = tid + 256 * i;
                int r = idx >> 4, c = (idx & 15) << 3;
                CPA(sptr(&Bs[buf][r * 136 + c]),
                    Bm + (size_t)((kt << 5) + r) * ldb + bcol + c);
            }
        }
    };

    load_stage(0, 0); CPCOMMIT();
    int buf = 0;
    for (int kt = 0; kt < KT; kt++) {
        if (kt + 1 < KT) { load_stage(buf ^ 1, kt + 1); CPCOMMIT(); CPWAIT1(); }
        else             { CPWAIT0(); }
        __syncthreads();

#pragma unroll
        for (int kk = 0; kk < 32; kk += 16) {
            uint32_t a[4][4];
#pragma unroll
            for (int mt = 0; mt < 4; mt++) {
                int moff = (lane & 7) + ((lane >> 3) & 1) * 8;
                int koff = (lane >> 4) * 8;
                uint32_t addr = sptr(&As[buf][(wm + mt * 16 + moff) * 40 + kk + koff]);
                asm volatile("ldmatrix.sync.aligned.m8n8.x4.shared.b16 {%0,%1,%2,%3},[%4];"
                    : "=r"(a[mt][0]), "=r"(a[mt][1]), "=r"(a[mt][2]), "=r"(a[mt][3]) : "r"(addr));
            }
            uint32_t b[2][4];
#pragma unroll
            for (int np = 0; np < 2; np++) {
                int q = lane >> 3;
                if (BT) {
                    int noff = ((q >> 1) * 8) + (lane & 7);
                    int koff = (q & 1) * 8;
                    uint32_t addr = sptr(&Bs[buf][(wn + np * 16 + noff) * 40 + kk + koff]);
                    asm volatile("ldmatrix.sync.aligned.m8n8.x4.shared.b16 {%0,%1,%2,%3},[%4];"
                        : "=r"(b[np][0]), "=r"(b[np][1]), "=r"(b[np][2]), "=r"(b[np][3]) : "r"(addr));
                } else {
                    int koff = (q & 1) * 8 + (lane & 7);
                    int noff = (q >> 1) * 8;
                    uint32_t addr = sptr(&Bs[buf][(kk + koff) * 136 + wn + np * 16 + noff]);
                    asm volatile("ldmatrix.sync.aligned.m8n8.x4.trans.shared.b16 {%0,%1,%2,%3},[%4];"
                        : "=r"(b[np][0]), "=r"(b[np][1]), "=r"(b[np][2]), "=r"(b[np][3]) : "r"(addr));
                }
            }
#pragma unroll
            for (int mt = 0; mt < 4; mt++)
#pragma unroll
                for (int nt = 0; nt < 4; nt++) {
                    uint32_t b0 = b[nt >> 1][(nt & 1) * 2 + 0];
                    uint32_t b1 = b[nt >> 1][(nt & 1) * 2 + 1];
                    asm volatile("mma.sync.aligned.m16n8k16.row.col.f32.bf16.bf16.f32 "
                        "{%0,%1,%2,%3},{%4,%5,%6,%7},{%8,%9},{%0,%1,%2,%3};"
                        : "+f"(acc[mt][nt][0]), "+f"(acc[mt][nt][1]),
                          "+f"(acc[mt][nt][2]), "+f"(acc[mt][nt][3])
                        : "r"(a[mt][0]), "r"(a[mt][1]), "r"(a[mt][2]), "r"(a[mt][3]),
                          "r"(b0), "r"(b1));
                }
        }
        __syncthreads();
        buf ^= 1;
    }

    // epilogue
#pragma unroll
    for (int mt = 0; mt < 4; mt++)
#pragma unroll
        for (int nt = 0; nt < 4; nt++)
#pragma unroll
            for (int h = 0; h < 2; h++) {
                int row = brow + wm + mt * 16 + (lane >> 2) + h * 8;
                int col = bcol + wn + nt * 8 + (lane & 3) * 2;
                float v0 = acc[mt][nt][h * 2 + 0];
                float v1 = acc[mt][nt][h * 2 + 1];
                if (bias) { v0 += bias[col]; v1 += bias[col + 1]; }
                v0 *= alpha; v1 *= alpha;
                if (MASK) {
                    bool w0 = (row >= col)     && (row - col     < W_);
                    bool w1 = (row >= col + 1) && (row - col - 1 < W_);
                    v0 = w0 ? -FLT_MAX : v0;
                    v1 = w1 ? -FLT_MAX : v1;
                }
                *(float2*)(C + (size_t)row * ldc + col) = make_float2(v0, v1);
            }
}

// ----------------------------- launch -----------------------------------------
extern "C" void kernel_launch(void* const* d_in, const int* in_sizes, int n_in,
                              void* d_out, int out_size) {
    const float* x        = (const float*)d_in[0];
    const float* ln_scale = (const float*)d_in[1];
    const float* ln_bias  = (const float*)d_in[2];
    const float* wq       = (const float*)d_in[3];
    const float* bq       = (const float*)d_in[4];
    const float* wk       = (const float*)d_in[5];
    const float* bk       = (const float*)d_in[6];
    const float* wv       = (const float*)d_in[7];
    const float* bv       = (const float*)d_in[8];
    const float* wo       = (const float*)d_in[9];
    const float* bo       = (const float*)d_in[10];
    float* out = (float*)d_out;

    __nv_bfloat16 *ypv, *wqpv, *wkpv, *wvpv, *wopv, *qpv, *kpv, *vpv, *attnpv, *ctxpv;
    float *qv, *kv, *vv, *sv, *cv;
    cudaGetSymbolAddress((void**)&ypv, g_yp);
    cudaGetSymbolAddress((void**)&wqpv, g_wqp);
    cudaGetSymbolAddress((void**)&wkpv, g_wkp);
    cudaGetSymbolAddress((void**)&wvpv, g_wvp);
    cudaGetSymbolAddress((void**)&wopv, g_wop);
    cudaGetSymbolAddress((void**)&qv, g_q);
    cudaGetSymbolAddress((void**)&kv, g_k);
    cudaGetSymbolAddress((void**)&vv, g_v);
    cudaGetSymbolAddress((void**)&qpv, g_qp);
    cudaGetSymbolAddress((void**)&kpv, g_kp);
    cudaGetSymbolAddress((void**)&vpv, g_vp);
    cudaGetSymbolAddress((void**)&sv, g_s);
    cudaGetSymbolAddress((void**)&attnpv, g_attnp);
    cudaGetSymbolAddress((void**)&cv, g_ctx);
    cudaGetSymbolAddress((void**)&ctxpv, g_ctxp);

    // 1) LayerNorm + aug
    ln_aug_kernel<<<ROWS_, 256>>>(x, ln_scale, ln_bias);

    // 2) weight augs
    int wElems = H_ * H_;
    w_aug_kernel<<<wElems / 256, 256>>>(wq, wqpv);
    w_aug_kernel<<<wElems / 256, 256>>>(wk, wkpv);
    w_aug_kernel<<<wElems / 256, 256>>>(wv, wvpv);
    w_aug_kernel<<<wElems / 256, 256>>>(wo, wopv);

    // 3) projections: [4096 x 6144] x [6144 x 2048]
    dim3 gProj(H_ / 128, ROWS_ / 128, 1);
    mma_gemm<false, false><<<gProj, 256>>>(ypv, wqpv, bq, qv, K3H, K3H, H_, H_,
                                           0, 0, 0, 0, 0, 0, QK_SCALE);
    mma_gemm<false, false><<<gProj, 256>>>(ypv, wkpv, bk, kv, K3H, K3H, H_, H_,
                                           0, 0, 0, 0, 0, 0, 1.0f);
    mma_gemm<false, false><<<gProj, 256>>>(ypv, wvpv, bv, vv, K3H, K3H, H_, H_,
                                           0, 0, 0, 0, 0, 0, 1.0f);

    // 4) q/k/v augs
    int qkElems = B_ * S_ * NH_ * HD_;
    qk_aug_kernel<<<qkElems / 256, 256>>>(qv, qpv, 1);   // A-pattern (hi,hi,lo)
    qk_aug_kernel<<<qkElems / 256, 256>>>(kv, kpv, 0);   // B-pattern (hi,lo,hi)
    v_aug_kernel<<<qkElems / 256, 256>>>(vv, vpv);

    // 5) scores = q' k'^T (NT) with inverted-window mask
    dim3 gScores(S_ / 128, S_ / 128, B_ * NH_);
    mma_gemm<true, true><<<gScores, 256>>>(qpv, kpv, (const float*)nullptr, sv,
                                           K3D, K3D, K3D, S_,
                                           (long)NH_ * S_ * K3D, (long)S_ * K3D,
                                           (long)NH_ * S_ * K3D, (long)S_ * K3D,
                                           (long)NH_ * S_ * S_,  (long)S_ * S_,
                                           1.0f);

    // 6) softmax + aug
    softmax_aug_kernel<<<B_ * NH_ * S_, 256>>>();

    // 7) ctx = attn' v' : per (b,n) [2048 x 6144] x [6144 x 128]
    dim3 gPV(1, S_ / 128, B_ * NH_);
    mma_gemm<false, false><<<gPV, 256>>>(attnpv, vpv, (const float*)nullptr, cv,
                                         K3H, K3H, H_, H_,
                                         (long)NH_ * S_ * K3H, (long)S_ * K3H,
                                         (long)K3H * H_, (long)HD_,
                                         (long)S_ * H_, (long)HD_,
                                         1.0f);

    // 8) ctx aug
    ctx_aug_kernel<<<(ROWS_ * H_) / 256, 256>>>(cv, ctxpv);

    // 9) out = ctx' wo' + bo
    mma_gemm<false, false><<<gProj, 256>>>(ctxpv, wopv, bo, out, K3H, K3H, H_, H_,
                                           0, 0, 0, 0, 0, 0, 1.0f);
}